// round 4
// baseline (speedup 1.0000x reference)
#include <cuda_runtime.h>
#include <math_constants.h>
#include <cstdint>

typedef unsigned long long ull;

#define NPTS 65536
#define KK   64
#define CH   128         // chunks over N for kernel A
#define LPB  (NPTS/CH)   // 512 points per block in kernel A
#define BB   8
#define LOG2E 1.4426950408889634f
#define PI_CONST ((1.0f + 1e-8f) / 65536.0f)
#define INV_DENOM (1.0f / (1.0f + 2e-8f))

// Scratch (device globals: no allocation allowed)
__device__ float g_part[16][CH][KK][4];   // [bt][chunk][k][{S, Sx, Sy, Sz}]
__device__ float g_RT[BB][12];            // 9 R (row major) + 3 T

__device__ __forceinline__ float ex2f(float x) {
    float r; asm("ex2.approx.f32 %0, %1;" : "=f"(r) : "f"(x)); return r;
}
__device__ __forceinline__ float lg2f(float x) {
    float r; asm("lg2.approx.f32 %0, %1;" : "=f"(r) : "f"(x)); return r;
}

// ---- packed f32x2 helpers (Blackwell) ----
__device__ __forceinline__ ull fma2(ull a, ull b, ull c) {
    ull d; asm("fma.rn.f32x2 %0, %1, %2, %3;" : "=l"(d) : "l"(a), "l"(b), "l"(c)); return d;
}
__device__ __forceinline__ ull mul2(ull a, ull b) {
    ull d; asm("mul.rn.f32x2 %0, %1, %2;" : "=l"(d) : "l"(a), "l"(b)); return d;
}
__device__ __forceinline__ ull add2(ull a, ull b) {
    ull d; asm("add.rn.f32x2 %0, %1, %2;" : "=l"(d) : "l"(a), "l"(b)); return d;
}
__device__ __forceinline__ ull pack2(float lo, float hi) {
    ull r; asm("mov.b64 %0, {%1, %2};" : "=l"(r) : "f"(lo), "f"(hi)); return r;
}
__device__ __forceinline__ void unpack2(ull v, float& lo, float& hi) {
    asm("mov.b64 {%0, %1}, %2;" : "=f"(lo), "=f"(hi) : "l"(v));
}

union F4u { float4 f; ull u[2]; };

// ---------------------------------------------------------------------------
// Kernel A: per (b, tensor, chunk): plain-sum softmax numerators for all K=64.
// No max-tracking (logits bounded; fp32 range ample). Packed f32x2 math.
// Block = 256 threads = 64 k-lanes x 4 point-slots; 8 blocks/SM forced.
// ---------------------------------------------------------------------------
__global__ void __launch_bounds__(256, 8) kA(const float* __restrict__ tmpl,
                                             const float* __restrict__ src,
                                             const float* __restrict__ W)
{
    __shared__ float sm[3 * LPB];   // [x(512) | y(512) | z(512)]
    const int bt = blockIdx.y;
    const int b  = bt & 7;
    const int t  = bt >> 3;
    const float* f = (t ? src : tmpl) + (size_t)b * 3 * NPTS;
    const int base = blockIdx.x * LPB;
    const int tid  = threadIdx.x;

    if (tid < LPB/4) {
        ((float4*)sm)[tid]             = ((const float4*)(f + base))[tid];
        ((float4*)sm)[LPB/4 + tid]     = ((const float4*)(f + NPTS + base))[tid];
        ((float4*)sm)[2*(LPB/4) + tid] = ((const float4*)(f + 2*NPTS + base))[tid];
    }
    __syncthreads();

    const int k    = tid & 63;
    const int slot = tid >> 6;
    const float wx = W[k]       * LOG2E;
    const float wy = W[64 + k]  * LOG2E;
    const float wz = W[128 + k] * LOG2E;
    const ull wx2 = pack2(wx, wx), wy2 = pack2(wy, wy), wz2 = pack2(wz, wz);

    ull S2 = 0, AX2 = 0, AY2 = 0, AZ2 = 0;

    const F4u* X = (const F4u*)sm + slot * (LPB/16);                 // 32 float4/slot
    const F4u* Y = (const F4u*)(sm + LPB) + slot * (LPB/16);
    const F4u* Z = (const F4u*)(sm + 2*LPB) + slot * (LPB/16);

    #pragma unroll 8
    for (int i = 0; i < LPB/16; i++) {
        F4u px = X[i], py = Y[i], pz = Z[i];
        ull l01 = fma2(wx2, px.u[0], fma2(wy2, py.u[0], mul2(wz2, pz.u[0])));
        ull l23 = fma2(wx2, px.u[1], fma2(wy2, py.u[1], mul2(wz2, pz.u[1])));
        float f0, f1, f2, f3;
        unpack2(l01, f0, f1); unpack2(l23, f2, f3);
        ull e01 = pack2(ex2f(f0), ex2f(f1));
        ull e23 = pack2(ex2f(f2), ex2f(f3));
        S2  = add2(S2, e01);               S2  = add2(S2, e23);
        AX2 = fma2(e01, px.u[0], AX2);     AX2 = fma2(e23, px.u[1], AX2);
        AY2 = fma2(e01, py.u[0], AY2);     AY2 = fma2(e23, py.u[1], AY2);
        AZ2 = fma2(e01, pz.u[0], AZ2);     AZ2 = fma2(e23, pz.u[1], AZ2);
    }

    float s0, s1, x0, x1, y0, y1, z0, z1;
    unpack2(S2, s0, s1); unpack2(AX2, x0, x1); unpack2(AY2, y0, y1); unpack2(AZ2, z0, z1);
    float S = s0 + s1, AX = x0 + x1, AY = y0 + y1, AZ = z0 + z1;

    __syncthreads();                        // done reading point smem
    sm[tid] = S; sm[256 + tid] = AX; sm[512 + tid] = AY; sm[768 + tid] = AZ;
    __syncthreads();
    if (slot == 0) {
        float TS = 0.f, TX = 0.f, TY = 0.f, TZ = 0.f;
        #pragma unroll
        for (int o = 0; o < 4; o++) {
            int j = o * 64 + k;
            TS += sm[j]; TX += sm[256 + j]; TY += sm[512 + j]; TZ += sm[768 + j];
        }
        float* p = g_part[bt][blockIdx.x][k];
        p[0] = TS; p[1] = TX; p[2] = TY; p[3] = TZ;
    }
}

// ---------------------------------------------------------------------------
// Kernel BC (fused): reduce chunks -> mu, then per-batch 3x3 polar + R,T.
// ---------------------------------------------------------------------------
__device__ void polar3(const float* Win, float* Q)
{
    float X[9];
    #pragma unroll
    for (int i = 0; i < 9; i++) X[i] = Win[i];
    #pragma unroll 1
    for (int it = 0; it < 18; it++) {
        float c00 = X[4]*X[8] - X[5]*X[7];
        float c01 = X[5]*X[6] - X[3]*X[8];
        float c02 = X[3]*X[7] - X[4]*X[6];
        float c10 = X[2]*X[7] - X[1]*X[8];
        float c11 = X[0]*X[8] - X[2]*X[6];
        float c12 = X[1]*X[6] - X[0]*X[7];
        float c20 = X[1]*X[5] - X[2]*X[4];
        float c21 = X[2]*X[3] - X[0]*X[5];
        float c22 = X[0]*X[4] - X[1]*X[3];
        float det = X[0]*c00 + X[1]*c01 + X[2]*c02;
        float g  = ex2f(-0.3333333333f * lg2f(fabsf(det)));  // |det|^(-1/3)
        float h  = 0.5f * g;
        float h2 = __fdividef(0.5f, g * det);
        X[0] = h*X[0] + h2*c00; X[1] = h*X[1] + h2*c01; X[2] = h*X[2] + h2*c02;
        X[3] = h*X[3] + h2*c10; X[4] = h*X[4] + h2*c11; X[5] = h*X[5] + h2*c12;
        X[6] = h*X[6] + h2*c20; X[7] = h*X[7] + h2*c21; X[8] = h*X[8] + h2*c22;
    }
    #pragma unroll
    for (int i = 0; i < 9; i++) Q[i] = X[i];
}

__global__ void __launch_bounds__(128) kBC()
{
    __shared__ float mus[2][KK][3];   // [t][k][d]
    const int b = blockIdx.x;
    const int tid = threadIdx.x;
    const int t  = tid >> 6;
    const int k  = tid & 63;
    const int bt = t * 8 + b;

    float S = 0.f, AX = 0.f, AY = 0.f, AZ = 0.f;
    #pragma unroll 8
    for (int c = 0; c < CH; c++) {
        float4 p = *(const float4*)g_part[bt][c][k];
        S += p.x; AX += p.y; AY += p.z; AZ += p.w;
    }
    float inv = INV_DENOM / S;
    mus[t][k][0] = AX * inv;
    mus[t][k][1] = AY * inv;
    mus[t][k][2] = AZ * inv;
    __syncthreads();

    if (tid < 32) {
        const int lane = tid;
        float ms0[3], ms1[3], mt0[3], mt1[3];
        #pragma unroll
        for (int d = 0; d < 3; d++) {
            ms0[d] = mus[1][lane][d];      ms1[d] = mus[1][lane + 32][d];
            mt0[d] = mus[0][lane][d];      mt1[d] = mus[0][lane + 32][d];
        }
        float ss[3], st[3];
        #pragma unroll
        for (int d = 0; d < 3; d++) { ss[d] = ms0[d] + ms1[d]; st[d] = mt0[d] + mt1[d]; }
        #pragma unroll
        for (int off = 16; off; off >>= 1)
            #pragma unroll
            for (int d = 0; d < 3; d++) {
                ss[d] += __shfl_xor_sync(0xffffffffu, ss[d], off);
                st[d] += __shfl_xor_sync(0xffffffffu, st[d], off);
            }
        float cx[3], cy[3];
        #pragma unroll
        for (int d = 0; d < 3; d++) { cx[d] = PI_CONST * ss[d]; cy[d] = PI_CONST * st[d]; }

        float Wm[9];
        #pragma unroll
        for (int d = 0; d < 3; d++)
            #pragma unroll
            for (int e = 0; e < 3; e++)
                Wm[d*3+e] = (mt0[d] - cy[d]) * (ms0[e] - cx[e])
                          + (mt1[d] - cy[d]) * (ms1[e] - cx[e]);
        #pragma unroll
        for (int off = 16; off; off >>= 1)
            #pragma unroll
            for (int i = 0; i < 9; i++)
                Wm[i] += __shfl_xor_sync(0xffffffffu, Wm[i], off);

        if (lane == 0) {
            #pragma unroll
            for (int i = 0; i < 9; i++) Wm[i] *= PI_CONST;
            float Q[9];
            polar3(Wm, Q);
            float det = Q[0]*(Q[4]*Q[8]-Q[5]*Q[7])
                      - Q[1]*(Q[3]*Q[8]-Q[5]*Q[6])
                      + Q[2]*(Q[3]*Q[7]-Q[4]*Q[6]);
            if (det < 0.f) { Q[2] = -Q[2]; Q[5] = -Q[5]; Q[8] = -Q[8]; }
            float T0 = cy[0] - (Q[0]*cx[0] + Q[1]*cx[1] + Q[2]*cx[2]);
            float T1 = cy[1] - (Q[3]*cx[0] + Q[4]*cx[1] + Q[5]*cx[2]);
            float T2 = cy[2] - (Q[6]*cx[0] + Q[7]*cx[1] + Q[8]*cx[2]);
            float* rt = g_RT[b];
            #pragma unroll
            for (int i = 0; i < 9; i++) rt[i] = Q[i];
            rt[9] = T0; rt[10] = T1; rt[11] = T2;
        }
    }
}

// ---------------------------------------------------------------------------
// Kernel D: aligned[b,n,:] = R * src_pts[b,n,:] + T.
// ---------------------------------------------------------------------------
__global__ void __launch_bounds__(128) kD(const float* __restrict__ src,
                                          float* __restrict__ out)
{
    __shared__ float4 so[384];
    __shared__ float rt[12];
    const int b = blockIdx.x >> 7;
    const int tile = blockIdx.x & 127;
    const int tid = threadIdx.x;

    const float* f = src + (size_t)b * 3 * NPTS + tile * 512;
    float4 px = *(const float4*)(f + tid * 4);
    float4 py = *(const float4*)(f + NPTS + tid * 4);
    float4 pz = *(const float4*)(f + 2*NPTS + tid * 4);

    if (tid < 12) rt[tid] = g_RT[b][tid];
    __syncthreads();

    float r0 = rt[0], r1 = rt[1], r2 = rt[2];
    float r3 = rt[3], r4 = rt[4], r5 = rt[5];
    float r6 = rt[6], r7 = rt[7], r8 = rt[8];
    float t0 = rt[9], t1 = rt[10], t2 = rt[11];

    float X[4] = {px.x, px.y, px.z, px.w};
    float Y[4] = {py.x, py.y, py.z, py.w};
    float Z[4] = {pz.x, pz.y, pz.z, pz.w};
    float o[12];
    #pragma unroll
    for (int j = 0; j < 4; j++) {
        o[j*3 + 0] = fmaf(r0, X[j], fmaf(r1, Y[j], fmaf(r2, Z[j], t0)));
        o[j*3 + 1] = fmaf(r3, X[j], fmaf(r4, Y[j], fmaf(r5, Z[j], t1)));
        o[j*3 + 2] = fmaf(r6, X[j], fmaf(r7, Y[j], fmaf(r8, Z[j], t2)));
    }
    #pragma unroll
    for (int j = 0; j < 3; j++)
        so[tid*3 + j] = make_float4(o[j*4+0], o[j*4+1], o[j*4+2], o[j*4+3]);
    __syncthreads();

    float4* ob = (float4*)(out + ((size_t)b * NPTS + tile * 512) * 3);
    #pragma unroll
    for (int i = tid; i < 384; i += 128) ob[i] = so[i];
}

// ---------------------------------------------------------------------------
extern "C" void kernel_launch(void* const* d_in, const int* in_sizes, int n_in,
                              void* d_out, int out_size)
{
    const float* tmpl = (const float*)d_in[0];   // (8,3,65536)
    const float* src  = (const float*)d_in[1];   // (8,3,65536)
    const float* W    = (const float*)d_in[2];   // (3,64)
    float* out        = (float*)d_out;           // (8,65536,3)

    kA<<<dim3(CH, 16), 256>>>(tmpl, src, W);
    kBC<<<BB, 128>>>();
    kD<<<BB * (NPTS / 512), 128>>>(src, out);
}

// round 5
// speedup vs baseline: 1.1541x; 1.1541x over previous
#include <cuda_runtime.h>
#include <math_constants.h>
#include <cstdint>

typedef unsigned long long ull;

#define NPTS 65536
#define KK   64
#define CH   64          // chunks over N for kernel A
#define LPB  (NPTS/CH)   // 1024 points per block in kernel A
#define BB   8
#define LOG2E 1.4426950408889634f
#define PI_CONST ((1.0f + 1e-8f) / 65536.0f)
#define INV_DENOM (1.0f / (1.0f + 2e-8f))

// Scratch (device globals: no allocation allowed)
__device__ float g_part[16][CH][KK][4];   // [bt][chunk][k][{S, Sx, Sy, Sz}]
__device__ float g_RT[BB][12];            // 9 R (row major) + 3 T

__device__ __forceinline__ float ex2f(float x) {
    float r; asm("ex2.approx.f32 %0, %1;" : "=f"(r) : "f"(x)); return r;
}
__device__ __forceinline__ float lg2f(float x) {
    float r; asm("lg2.approx.f32 %0, %1;" : "=f"(r) : "f"(x)); return r;
}

// ---- packed f32x2 helpers (Blackwell) ----
__device__ __forceinline__ ull fma2(ull a, ull b, ull c) {
    ull d; asm("fma.rn.f32x2 %0, %1, %2, %3;" : "=l"(d) : "l"(a), "l"(b), "l"(c)); return d;
}
__device__ __forceinline__ ull mul2(ull a, ull b) {
    ull d; asm("mul.rn.f32x2 %0, %1, %2;" : "=l"(d) : "l"(a), "l"(b)); return d;
}
__device__ __forceinline__ ull add2(ull a, ull b) {
    ull d; asm("add.rn.f32x2 %0, %1, %2;" : "=l"(d) : "l"(a), "l"(b)); return d;
}
__device__ __forceinline__ ull pack2(float lo, float hi) {
    ull r; asm("mov.b64 %0, {%1, %2};" : "=l"(r) : "f"(lo), "f"(hi)); return r;
}
// ex2 on both halves of a packed pair, in one asm window (helps ptxas pair regs)
__device__ __forceinline__ ull ex2_2(ull v) {
    ull r;
    asm("{\n\t.reg .f32 lo, hi;\n\t"
        "mov.b64 {lo, hi}, %1;\n\t"
        "ex2.approx.f32 lo, lo;\n\t"
        "ex2.approx.f32 hi, hi;\n\t"
        "mov.b64 %0, {lo, hi};\n\t}"
        : "=l"(r) : "l"(v));
    return r;
}

union F4u { float4 f; ull u[2]; };

// ---------------------------------------------------------------------------
// Kernel A: per (b, tensor, chunk): plain-sum softmax numerators for all K=64.
// Block = 256 threads = 64 k-lanes x 4 point-slots; smem point staging with
// one-iteration register prefetch; packed f32x2 math throughout.
// ---------------------------------------------------------------------------
__global__ void __launch_bounds__(256) kA(const float* __restrict__ tmpl,
                                          const float* __restrict__ src,
                                          const float* __restrict__ W)
{
    __shared__ float sm[3 * LPB];   // x | y | z  (12 KB)
    const int bt = blockIdx.y;
    const int b  = bt & 7;
    const int t  = bt >> 3;
    const float* f = (t ? src : tmpl) + (size_t)b * 3 * NPTS;
    const int base = blockIdx.x * LPB;
    const int tid  = threadIdx.x;

    ((float4*)sm)[tid]       = ((const float4*)(f + base))[tid];
    ((float4*)sm)[256 + tid] = ((const float4*)(f + NPTS + base))[tid];
    ((float4*)sm)[512 + tid] = ((const float4*)(f + 2*NPTS + base))[tid];
    __syncthreads();

    const int k    = tid & 63;
    const int slot = tid >> 6;
    const float wx = W[k]       * LOG2E;
    const float wy = W[64 + k]  * LOG2E;
    const float wz = W[128 + k] * LOG2E;
    const ull wx2 = pack2(wx, wx), wy2 = pack2(wy, wy), wz2 = pack2(wz, wz);

    ull S2 = 0, AX2 = 0, AY2 = 0, AZ2 = 0;

    const F4u* X = (const F4u*)sm + slot * (LPB/16);                 // 64 F4u/slot
    const F4u* Y = (const F4u*)(sm + LPB) + slot * (LPB/16);
    const F4u* Z = (const F4u*)(sm + 2*LPB) + slot * (LPB/16);

    F4u px = X[0], py = Y[0], pz = Z[0];
    #pragma unroll 8
    for (int i = 0; i < LPB/16; i++) {
        const int j = (i + 1 < LPB/16) ? i + 1 : 0;
        F4u nx = X[j], ny = Y[j], nz = Z[j];      // prefetch next triple
        ull l01 = fma2(wx2, px.u[0], fma2(wy2, py.u[0], mul2(wz2, pz.u[0])));
        ull l23 = fma2(wx2, px.u[1], fma2(wy2, py.u[1], mul2(wz2, pz.u[1])));
        ull e01 = ex2_2(l01);
        ull e23 = ex2_2(l23);
        S2  = add2(S2, e01);               S2  = add2(S2, e23);
        AX2 = fma2(e01, px.u[0], AX2);     AX2 = fma2(e23, px.u[1], AX2);
        AY2 = fma2(e01, py.u[0], AY2);     AY2 = fma2(e23, py.u[1], AY2);
        AZ2 = fma2(e01, pz.u[0], AZ2);     AZ2 = fma2(e23, pz.u[1], AZ2);
        px = nx; py = ny; pz = nz;
    }

    float s0, s1, x0, x1, y0, y1, z0, z1;
    asm("mov.b64 {%0, %1}, %2;" : "=f"(s0), "=f"(s1) : "l"(S2));
    asm("mov.b64 {%0, %1}, %2;" : "=f"(x0), "=f"(x1) : "l"(AX2));
    asm("mov.b64 {%0, %1}, %2;" : "=f"(y0), "=f"(y1) : "l"(AY2));
    asm("mov.b64 {%0, %1}, %2;" : "=f"(z0), "=f"(z1) : "l"(AZ2));
    float S = s0 + s1, AX = x0 + x1, AY = y0 + y1, AZ = z0 + z1;

    __syncthreads();                        // done reading point smem
    sm[tid] = S; sm[256 + tid] = AX; sm[512 + tid] = AY; sm[768 + tid] = AZ;
    __syncthreads();
    if (slot == 0) {
        float TS = 0.f, TX = 0.f, TY = 0.f, TZ = 0.f;
        #pragma unroll
        for (int o = 0; o < 4; o++) {
            int j = o * 64 + k;
            TS += sm[j]; TX += sm[256 + j]; TY += sm[512 + j]; TZ += sm[768 + j];
        }
        float* p = g_part[bt][blockIdx.x][k];
        p[0] = TS; p[1] = TX; p[2] = TY; p[3] = TZ;
    }
}

// ---------------------------------------------------------------------------
// Kernel BC (fused, wide): one block per batch, 1024 threads.
// Stage 1: 8 lanes per (t,k) item reduce the 64 chunks (8 loads each) and
// shuffle-combine. Stage 2: warp 0 computes cross-covariance + polar + R,T.
// ---------------------------------------------------------------------------
__device__ void polar3(const float* Win, float* Q)
{
    float X[9];
    #pragma unroll
    for (int i = 0; i < 9; i++) X[i] = Win[i];
    #pragma unroll 1
    for (int it = 0; it < 18; it++) {
        float c00 = X[4]*X[8] - X[5]*X[7];
        float c01 = X[5]*X[6] - X[3]*X[8];
        float c02 = X[3]*X[7] - X[4]*X[6];
        float c10 = X[2]*X[7] - X[1]*X[8];
        float c11 = X[0]*X[8] - X[2]*X[6];
        float c12 = X[1]*X[6] - X[0]*X[7];
        float c20 = X[1]*X[5] - X[2]*X[4];
        float c21 = X[2]*X[3] - X[0]*X[5];
        float c22 = X[0]*X[4] - X[1]*X[3];
        float det = X[0]*c00 + X[1]*c01 + X[2]*c02;
        float g  = ex2f(-0.3333333333f * lg2f(fabsf(det)));  // |det|^(-1/3)
        float h  = 0.5f * g;
        float h2 = __fdividef(0.5f, g * det);
        X[0] = h*X[0] + h2*c00; X[1] = h*X[1] + h2*c01; X[2] = h*X[2] + h2*c02;
        X[3] = h*X[3] + h2*c10; X[4] = h*X[4] + h2*c11; X[5] = h*X[5] + h2*c12;
        X[6] = h*X[6] + h2*c20; X[7] = h*X[7] + h2*c21; X[8] = h*X[8] + h2*c22;
    }
    #pragma unroll
    for (int i = 0; i < 9; i++) Q[i] = X[i];
}

__global__ void __launch_bounds__(1024) kBC()
{
    __shared__ float mus[2][KK][3];   // [t][k][d]
    const int b = blockIdx.x;
    const int tid = threadIdx.x;
    const int item  = tid >> 3;       // 0..127
    const int lane8 = tid & 7;
    const int t  = item >> 6;
    const int k  = item & 63;
    const int bt = t * 8 + b;

    float S = 0.f, AX = 0.f, AY = 0.f, AZ = 0.f;
    #pragma unroll
    for (int j = 0; j < 8; j++) {
        float4 p = *(const float4*)g_part[bt][lane8 + 8 * j][k];
        S += p.x; AX += p.y; AY += p.z; AZ += p.w;
    }
    #pragma unroll
    for (int off = 4; off; off >>= 1) {
        S  += __shfl_xor_sync(0xffffffffu, S,  off);
        AX += __shfl_xor_sync(0xffffffffu, AX, off);
        AY += __shfl_xor_sync(0xffffffffu, AY, off);
        AZ += __shfl_xor_sync(0xffffffffu, AZ, off);
    }
    if (lane8 == 0) {
        float inv = INV_DENOM / S;
        mus[t][k][0] = AX * inv;
        mus[t][k][1] = AY * inv;
        mus[t][k][2] = AZ * inv;
    }
    __syncthreads();

    if (tid < 32) {
        const int lane = tid;
        float ms0[3], ms1[3], mt0[3], mt1[3];
        #pragma unroll
        for (int d = 0; d < 3; d++) {
            ms0[d] = mus[1][lane][d];      ms1[d] = mus[1][lane + 32][d];
            mt0[d] = mus[0][lane][d];      mt1[d] = mus[0][lane + 32][d];
        }
        float ss[3], st[3];
        #pragma unroll
        for (int d = 0; d < 3; d++) { ss[d] = ms0[d] + ms1[d]; st[d] = mt0[d] + mt1[d]; }
        #pragma unroll
        for (int off = 16; off; off >>= 1)
            #pragma unroll
            for (int d = 0; d < 3; d++) {
                ss[d] += __shfl_xor_sync(0xffffffffu, ss[d], off);
                st[d] += __shfl_xor_sync(0xffffffffu, st[d], off);
            }
        float cx[3], cy[3];
        #pragma unroll
        for (int d = 0; d < 3; d++) { cx[d] = PI_CONST * ss[d]; cy[d] = PI_CONST * st[d]; }

        float Wm[9];
        #pragma unroll
        for (int d = 0; d < 3; d++)
            #pragma unroll
            for (int e = 0; e < 3; e++)
                Wm[d*3+e] = (mt0[d] - cy[d]) * (ms0[e] - cx[e])
                          + (mt1[d] - cy[d]) * (ms1[e] - cx[e]);
        #pragma unroll
        for (int off = 16; off; off >>= 1)
            #pragma unroll
            for (int i = 0; i < 9; i++)
                Wm[i] += __shfl_xor_sync(0xffffffffu, Wm[i], off);

        if (lane == 0) {
            #pragma unroll
            for (int i = 0; i < 9; i++) Wm[i] *= PI_CONST;
            float Q[9];
            polar3(Wm, Q);
            float det = Q[0]*(Q[4]*Q[8]-Q[5]*Q[7])
                      - Q[1]*(Q[3]*Q[8]-Q[5]*Q[6])
                      + Q[2]*(Q[3]*Q[7]-Q[4]*Q[6]);
            if (det < 0.f) { Q[2] = -Q[2]; Q[5] = -Q[5]; Q[8] = -Q[8]; }
            float T0 = cy[0] - (Q[0]*cx[0] + Q[1]*cx[1] + Q[2]*cx[2]);
            float T1 = cy[1] - (Q[3]*cx[0] + Q[4]*cx[1] + Q[5]*cx[2]);
            float T2 = cy[2] - (Q[6]*cx[0] + Q[7]*cx[1] + Q[8]*cx[2]);
            float* rt = g_RT[b];
            #pragma unroll
            for (int i = 0; i < 9; i++) rt[i] = Q[i];
            rt[9] = T0; rt[10] = T1; rt[11] = T2;
        }
    }
}

// ---------------------------------------------------------------------------
// Kernel D: aligned[b,n,:] = R * src_pts[b,n,:] + T.
// 256 blocks x 256 thr, 2048 pts/block: 6 upfront LDG.128/thread (high MLP).
// ---------------------------------------------------------------------------
__global__ void __launch_bounds__(256) kD(const float* __restrict__ src,
                                          float* __restrict__ out)
{
    __shared__ float4 so[1536];
    __shared__ float rt[12];
    const int b = blockIdx.x >> 5;
    const int tile = blockIdx.x & 31;
    const int tid = threadIdx.x;

    const float* f = src + (size_t)b * 3 * NPTS + tile * 2048;
    float4 px0 = ((const float4*)f)[tid];
    float4 px1 = ((const float4*)f)[256 + tid];
    float4 py0 = ((const float4*)(f + NPTS))[tid];
    float4 py1 = ((const float4*)(f + NPTS))[256 + tid];
    float4 pz0 = ((const float4*)(f + 2*NPTS))[tid];
    float4 pz1 = ((const float4*)(f + 2*NPTS))[256 + tid];

    if (tid < 12) rt[tid] = g_RT[b][tid];
    __syncthreads();

    float r0 = rt[0], r1 = rt[1], r2 = rt[2];
    float r3 = rt[3], r4 = rt[4], r5 = rt[5];
    float r6 = rt[6], r7 = rt[7], r8 = rt[8];
    float t0 = rt[9], t1 = rt[10], t2 = rt[11];

    #pragma unroll
    for (int h = 0; h < 2; h++) {
        float4 px = h ? px1 : px0, py = h ? py1 : py0, pz = h ? pz1 : pz0;
        float X[4] = {px.x, px.y, px.z, px.w};
        float Y[4] = {py.x, py.y, py.z, py.w};
        float Z[4] = {pz.x, pz.y, pz.z, pz.w};
        float o[12];
        #pragma unroll
        for (int j = 0; j < 4; j++) {
            o[j*3 + 0] = fmaf(r0, X[j], fmaf(r1, Y[j], fmaf(r2, Z[j], t0)));
            o[j*3 + 1] = fmaf(r3, X[j], fmaf(r4, Y[j], fmaf(r5, Z[j], t1)));
            o[j*3 + 2] = fmaf(r6, X[j], fmaf(r7, Y[j], fmaf(r8, Z[j], t2)));
        }
        #pragma unroll
        for (int j = 0; j < 3; j++)
            so[(h * 256 + tid) * 3 + j] = make_float4(o[j*4+0], o[j*4+1], o[j*4+2], o[j*4+3]);
    }
    __syncthreads();

    float4* ob = (float4*)(out + ((size_t)b * NPTS + tile * 2048) * 3);
    #pragma unroll
    for (int i = tid; i < 1536; i += 256) ob[i] = so[i];
}

// ---------------------------------------------------------------------------
extern "C" void kernel_launch(void* const* d_in, const int* in_sizes, int n_in,
                              void* d_out, int out_size)
{
    const float* tmpl = (const float*)d_in[0];   // (8,3,65536)
    const float* src  = (const float*)d_in[1];   // (8,3,65536)
    const float* W    = (const float*)d_in[2];   // (3,64)
    float* out        = (float*)d_out;           // (8,65536,3)

    kA<<<dim3(CH, 16), 256>>>(tmpl, src, W);
    kBC<<<BB, 1024>>>();
    kD<<<256, 256>>>(src, out);
}